// round 6
// baseline (speedup 1.0000x reference)
#include <cuda_runtime.h>
#include <cuda_fp16.h>
#include <math.h>

// CapsuleRouting: u (4,288,32,16,14,14) f32, a unused.
// out = concat(v (4,32,16,14,14), a_out (4,32,14,14))

#define BD 4      // batch
#define NB 288    // input capsules
#define NC 32     // output capsules (softmax axis)
#define NP 16     // pose dim
#define HW 196    // h*w
#define NCHUNK 4  // B-chunks in pass A
#define BCH (NB / NCHUNK)   // 72
#define EPSF 1e-5f

// F-kernel tiling
#define TH 28           // hw per block (7 tiles)
#define NPP 8           // p-pair lanes
#define FTHREADS (TH * NPP)   // 224
#define NCH2 10         // B-chunks in F pass
#define BCH2 29         // ceil(288/10)

// ---------------- scratch (static device globals) -----------------------------
__device__ __half g_u16[(size_t)BD * NB * NC * HW * NP];   // 231MB, layout (b,B,c,hw,p)
__device__ float  g_S0p[NCHUNK * BD * NC * NP * HW];
__device__ float  g_mxp[NCHUNK * BD * NC * HW];
__device__ float  g_mnp[NCHUNK * BD * NC * HW];
__device__ float  g_invd[BD * NC * HW];
__device__ __half g_vs[BD * NC * HW * NP];                 // v_s = invd*v, layout (b,c,hw,p)
__device__ float  g_r[(size_t)BD * NB * HW * NC];          // 28.9MB, layout (b,B,hw,c)
__device__ float  g_Sp[NCH2 * BD * NC * HW * NP];          // 16MB partial S, (chk,b,c,hw,p)

union HPack { __half2 h2[8]; uint4 u4[2]; };

// ---------------- Pass A1: norms -> chunked max/min; Sum_B u; emit u16 --------
__global__ void kA1(const float* __restrict__ u) {
    int t = blockIdx.x * blockDim.x + threadIdx.x;    // 100352
    int hw = t % HW;
    int rest = t / HW;
    int c = rest % NC; rest /= NC;
    int b = rest % BD;
    int ch = rest / BD;

    float s[NP];
#pragma unroll
    for (int p = 0; p < NP; p++) s[p] = 0.0f;
    float mx = -1e30f, mn = 1e30f;

    const float* up = u + ((size_t)((b * NB + ch * BCH) * NC + c)) * (NP * HW) + hw;
    size_t u16base = (((size_t)(b * NB + ch * BCH) * NC + c) * HW + hw) * NP;

    for (int i = 0; i < BCH; i++) {
        float x[NP];
        float nrm = EPSF;
#pragma unroll
        for (int p = 0; p < NP; p++) {
            x[p] = up[p * HW];
            s[p] += x[p];
            nrm += x[p] * x[p];
        }
        nrm = sqrtf(nrm);
        mx = fmaxf(mx, nrm);
        mn = fminf(mn, nrm);

        HPack pk;
#pragma unroll
        for (int j = 0; j < 8; j++) pk.h2[j] = __floats2half2_rn(x[2 * j], x[2 * j + 1]);
        uint4* dst = reinterpret_cast<uint4*>(g_u16 + u16base);
        dst[0] = pk.u4[0];
        dst[1] = pk.u4[1];

        up += (size_t)NC * NP * HW;          // next B
        u16base += (size_t)NC * HW * NP;
    }
    int o = (ch * BD + b) * NC + c;
#pragma unroll
    for (int p = 0; p < NP; p++) g_S0p[(o * NP + p) * HW + hw] = s[p];
    g_mxp[o * HW + hw] = mx;
    g_mnp[o * HW + hw] = mn;
}

// ---------------- Pass A2: combine chunks, inv_d, v0s = invd*squash(S0/32*invd)
__global__ void kA2() {
    int t = blockIdx.x * blockDim.x + threadIdx.x;    // 25088
    int hw = t % HW;
    int rest = t / HW;
    int c = rest % NC;
    int b = rest / NC;

    float s[NP];
#pragma unroll
    for (int p = 0; p < NP; p++) s[p] = 0.0f;
    float mx = -1e30f, mn = 1e30f;
#pragma unroll
    for (int ch = 0; ch < NCHUNK; ch++) {
        int o = (ch * BD + b) * NC + c;
        mx = fmaxf(mx, g_mxp[o * HW + hw]);
        mn = fminf(mn, g_mnp[o * HW + hw]);
#pragma unroll
        for (int p = 0; p < NP; p++) s[p] += g_S0p[(o * NP + p) * HW + hw];
    }
    float invd = 1.0f / (mx - mn);
    g_invd[(b * NC + c) * HW + hw] = invd;

    float nv = EPSF;
    const float scl = invd * (1.0f / (float)NC);   // uniform softmax weight 1/32
#pragma unroll
    for (int p = 0; p < NP; p++) { s[p] *= scl; nv += s[p] * s[p]; }
    nv = sqrtf(nv);
    float f = invd / (1.0f + nv);                  // fold invd into stored v_s
    HPack pk;
#pragma unroll
    for (int j = 0; j < 8; j++)
        pk.h2[j] = __floats2half2_rn(s[2 * j] * f, s[2 * j + 1] * f);
    uint4* dst = reinterpret_cast<uint4*>(g_vs + ((size_t)((b * NC + c) * HW + hw)) * NP);
    dst[0] = pk.u4[0];
    dst[1] = pk.u4[1];
}

// ---------------- Fused routing iteration: read u16 once ----------------------
// r_new = (r_old +) dot(u, v_s); w = softmax_c(r_new); S_partial += w*u
template <int PHASE>
__global__ void __launch_bounds__(FTHREADS, 2) kF() {
    int bid = blockIdx.x;
    int chk = bid % NCH2;
    int hwt = (bid / NCH2) % (HW / TH);
    int b   = bid / (NCH2 * (HW / TH));

    int tid = threadIdx.x;
    int pp  = tid & (NPP - 1);        // p-pair lane 0..7
    int hwl = tid >> 3;               // 0..27
    int hw  = hwt * TH + hwl;

    __shared__ __half2 vsm[NC][TH][NPP];
    for (int i = tid; i < NC * TH * NPP; i += FTHREADS) {
        int c  = i / (TH * NPP);
        int r  = i % (TH * NPP);
        int hl = r / NPP;
        int p2 = r % NPP;
        vsm[c][hl][p2] = *reinterpret_cast<const __half2*>(
            g_vs + (((size_t)(b * NC + c) * HW + hwt * TH + hl)) * NP + 2 * p2);
    }
    __syncthreads();

    float2 S2[NC];
#pragma unroll
    for (int c = 0; c < NC; c++) S2[c] = make_float2(0.0f, 0.0f);

    int B0 = chk * BCH2;
    int Bend = min(B0 + BCH2, NB);

    for (int B = B0; B < Bend; B++) {
        const __half* ub = g_u16 + ((((size_t)(b * NB + B) * NC) * HW + hw)) * NP + 2 * pp;
        __half2 x2[NC];
        float r4[4];

#pragma unroll
        for (int c = 0; c < NC; c++) {
            x2[c] = *reinterpret_cast<const __half2*>(ub + (size_t)c * (HW * NP));
            float2 xf = __half22float2(x2[c]);
            float2 vf = __half22float2(vsm[c][hwl][pp]);
            float t = xf.x * vf.x + xf.y * vf.y;
            t += __shfl_xor_sync(0xffffffffu, t, 1, 8);
            t += __shfl_xor_sync(0xffffffffu, t, 2, 8);
            t += __shfl_xor_sync(0xffffffffu, t, 4, 8);
            if ((c >> 2) == pp) r4[c & 3] = t;
        }

        float* rptr = g_r + (((size_t)(b * NB + B) * HW + hw)) * NC + 4 * pp;
        if (PHASE == 2) {
            float4 rp = *reinterpret_cast<const float4*>(rptr);
            r4[0] += rp.x; r4[1] += rp.y; r4[2] += rp.z; r4[3] += rp.w;
        } else {
            *reinterpret_cast<float4*>(rptr) = make_float4(r4[0], r4[1], r4[2], r4[3]);
        }

        // softmax over 32 c (4 per lane x 8 lanes)
        float m = fmaxf(fmaxf(r4[0], r4[1]), fmaxf(r4[2], r4[3]));
        m = fmaxf(m, __shfl_xor_sync(0xffffffffu, m, 1, 8));
        m = fmaxf(m, __shfl_xor_sync(0xffffffffu, m, 2, 8));
        m = fmaxf(m, __shfl_xor_sync(0xffffffffu, m, 4, 8));
        float w4[4];
        float ssum = 0.0f;
#pragma unroll
        for (int k = 0; k < 4; k++) { w4[k] = __expf(r4[k] - m); ssum += w4[k]; }
        ssum += __shfl_xor_sync(0xffffffffu, ssum, 1, 8);
        ssum += __shfl_xor_sync(0xffffffffu, ssum, 2, 8);
        ssum += __shfl_xor_sync(0xffffffffu, ssum, 4, 8);
        float inv = 1.0f / ssum;
#pragma unroll
        for (int k = 0; k < 4; k++) w4[k] *= inv;

        // accumulate S += w*u
#pragma unroll
        for (int c = 0; c < NC; c++) {
            float wc = __shfl_sync(0xffffffffu, w4[c & 3], c >> 2, 8);
            float2 xf = __half22float2(x2[c]);
            S2[c].x += wc * xf.x;
            S2[c].y += wc * xf.y;
        }
    }

    // write partial S
#pragma unroll
    for (int c = 0; c < NC; c++) {
        float2* dst = reinterpret_cast<float2*>(
            g_Sp + ((((size_t)(chk * BD + b) * NC + c) * HW + hw)) * NP + 2 * pp);
        *dst = S2[c];
    }
}

// ---------------- Combine partials: squash; emit v_s (half) or final output ---
template <int LAST>
__global__ void kC(float* __restrict__ vout, float* __restrict__ aout) {
    int t = blockIdx.x * blockDim.x + threadIdx.x;    // 25088
    int hw = t % HW;
    int rest = t / HW;
    int c = rest % NC;
    int b = rest / NC;

    float s[NP];
#pragma unroll
    for (int p = 0; p < NP; p++) s[p] = 0.0f;
#pragma unroll
    for (int chk = 0; chk < NCH2; chk++) {
        const float* sp = g_Sp + ((((size_t)(chk * BD + b) * NC + c) * HW + hw)) * NP;
#pragma unroll
        for (int p = 0; p < NP; p++) s[p] += sp[p];
    }
    float invd = g_invd[(b * NC + c) * HW + hw];
    float nv = EPSF;
#pragma unroll
    for (int p = 0; p < NP; p++) { s[p] *= invd; nv += s[p] * s[p]; }
    nv = sqrtf(nv);
    float f = 1.0f / (1.0f + nv);

    if (!LAST) {
        float fs = f * invd;                         // fold invd into stored v_s
        HPack pk;
#pragma unroll
        for (int j = 0; j < 8; j++)
            pk.h2[j] = __floats2half2_rn(s[2 * j] * fs, s[2 * j + 1] * fs);
        uint4* dst = reinterpret_cast<uint4*>(g_vs + ((size_t)((b * NC + c) * HW + hw)) * NP);
        dst[0] = pk.u4[0];
        dst[1] = pk.u4[1];
    } else {
        float an = EPSF;
#pragma unroll
        for (int p = 0; p < NP; p++) {
            float v = s[p] * f;
            vout[((b * NC + c) * NP + p) * HW + hw] = v;
            an += v * v;
        }
        aout[(b * NC + c) * HW + hw] = sqrtf(an);
    }
}

// ---------------- launch ------------------------------------------------------
extern "C" void kernel_launch(void* const* d_in, const int* in_sizes, int n_in,
                              void* d_out, int out_size) {
    const float* u = (const float*)d_in[0];
    float* out = (float*)d_out;
    float* out_v = out;                       // 4*32*16*196 = 401408
    float* out_a = out + BD * NC * NP * HW;   // 4*32*196    = 25088

    const int FGRID = BD * (HW / TH) * NCH2;  // 280

    kA1<<<392, 256>>>(u);                     // norms + Sum_B u + u16 transpose
    kA2<<<98, 256>>>();                       // inv_d, v0s
    kF<1><<<FGRID, FTHREADS>>>();             // r1 = dot(u,v0s); w1; S1 partials
    kC<0><<<98, 256>>>(nullptr, nullptr);     // v1s = invd*squash(invd*S1)
    kF<2><<<FGRID, FTHREADS>>>();             // r2 = r1+dot(u,v1s); w2; S2 partials
    kC<1><<<98, 256>>>(out_v, out_a);         // v2, a_out
}

// round 8
// speedup vs baseline: 1.0172x; 1.0172x over previous
#include <cuda_runtime.h>
#include <cuda_fp16.h>
#include <math.h>

// CapsuleRouting: u (4,288,32,16,14,14) f32, a unused.
// out = concat(v (4,32,16,14,14), a_out (4,32,14,14))
//
// Algebra: r logits are linear in v, so r2 = <u_s, v0+v1>; the 29MB r tensor
// is never materialized. u is transposed once to fp16 (b,B,c,hw,p); both
// routing iterations stream it exactly once each.

#define BD 4      // batch
#define NB 288    // input capsules
#define NC 32     // output capsules (softmax axis)
#define NP 16     // pose dim
#define HW 196    // h*w
#define NCHUNK 4  // B-chunks in pass A
#define BCH (NB / NCHUNK)   // 72
#define EPSF 1e-5f

// F-kernel tiling
#define TH 28           // hw per block (7 tiles)
#define NPP 8           // p-pair lanes
#define FTHREADS (TH * NPP)   // 224
#define NCH2 10         // B-chunks in F pass
#define BCH2 29         // ceil(288/10)

// ---------------- scratch (static device globals) -----------------------------
__device__ __half g_u16[(size_t)BD * NB * NC * HW * NP];   // 231MB, layout (b,B,c,hw,p)
__device__ float  g_S0p[NCHUNK * BD * NC * NP * HW];
__device__ float  g_mxp[NCHUNK * BD * NC * HW];
__device__ float  g_mnp[NCHUNK * BD * NC * HW];
__device__ float  g_invd[BD * NC * HW];
__device__ __half g_vs[BD * NC * HW * NP];                 // invd*v0, then invd*(v0+v1)
__device__ float  g_Sp[NCH2 * BD * NC * HW * NP];          // 16MB partial S, (chk,b,c,hw,p)

union HPack { __half2 h2[8]; uint4 u4[2]; };

// ---------------- Pass A1: norms -> chunked max/min; Sum_B u; emit u16 --------
__global__ void kA1(const float* __restrict__ u) {
    int t = blockIdx.x * blockDim.x + threadIdx.x;    // 100352
    int hw = t % HW;
    int rest = t / HW;
    int c = rest % NC; rest /= NC;
    int b = rest % BD;
    int ch = rest / BD;

    float s[NP];
#pragma unroll
    for (int p = 0; p < NP; p++) s[p] = 0.0f;
    float mx = -1e30f, mn = 1e30f;

    const float* up = u + ((size_t)((b * NB + ch * BCH) * NC + c)) * (NP * HW) + hw;
    size_t u16base = (((size_t)(b * NB + ch * BCH) * NC + c) * HW + hw) * NP;

    for (int i = 0; i < BCH; i++) {
        float x[NP];
        float nrm = EPSF;
#pragma unroll
        for (int p = 0; p < NP; p++) {
            x[p] = __ldcs(up + p * HW);
            s[p] += x[p];
            nrm += x[p] * x[p];
        }
        nrm = sqrtf(nrm);
        mx = fmaxf(mx, nrm);
        mn = fminf(mn, nrm);

        HPack pk;
#pragma unroll
        for (int j = 0; j < 8; j++) pk.h2[j] = __floats2half2_rn(x[2 * j], x[2 * j + 1]);
        uint4* dst = reinterpret_cast<uint4*>(g_u16 + u16base);
        __stcs(dst + 0, pk.u4[0]);
        __stcs(dst + 1, pk.u4[1]);

        up += (size_t)NC * NP * HW;          // next B
        u16base += (size_t)NC * HW * NP;
    }
    int o = (ch * BD + b) * NC + c;
#pragma unroll
    for (int p = 0; p < NP; p++) g_S0p[(o * NP + p) * HW + hw] = s[p];
    g_mxp[o * HW + hw] = mx;
    g_mnp[o * HW + hw] = mn;
}

// ---------------- Pass A2: combine chunks, inv_d, v0s = invd*squash(S0/32*invd)
__global__ void kA2() {
    int t = blockIdx.x * blockDim.x + threadIdx.x;    // 25088
    int hw = t % HW;
    int rest = t / HW;
    int c = rest % NC;
    int b = rest / NC;

    float s[NP];
#pragma unroll
    for (int p = 0; p < NP; p++) s[p] = 0.0f;
    float mx = -1e30f, mn = 1e30f;
#pragma unroll
    for (int ch = 0; ch < NCHUNK; ch++) {
        int o = (ch * BD + b) * NC + c;
        mx = fmaxf(mx, g_mxp[o * HW + hw]);
        mn = fminf(mn, g_mnp[o * HW + hw]);
#pragma unroll
        for (int p = 0; p < NP; p++) s[p] += g_S0p[(o * NP + p) * HW + hw];
    }
    float invd = 1.0f / (mx - mn);
    g_invd[(b * NC + c) * HW + hw] = invd;

    float nv = EPSF;
    const float scl = invd * (1.0f / (float)NC);   // uniform softmax weight 1/32
#pragma unroll
    for (int p = 0; p < NP; p++) { s[p] *= scl; nv += s[p] * s[p]; }
    nv = sqrtf(nv);
    float f = invd / (1.0f + nv);                  // fold invd into stored v_s
    HPack pk;
#pragma unroll
    for (int j = 0; j < 8; j++)
        pk.h2[j] = __floats2half2_rn(s[2 * j] * f, s[2 * j + 1] * f);
    uint4* dst = reinterpret_cast<uint4*>(g_vs + ((size_t)((b * NC + c) * HW + hw)) * NP);
    dst[0] = pk.u4[0];
    dst[1] = pk.u4[1];
}

// ---------------- Fused routing iteration: read u16 once ----------------------
// r = dot(u16, vs); w = softmax_c(r); S_partial = Sum_B w*u16
// (vs already contains invd*(v0[+v1]), so r carries the u_s scaling; no r store.)
__global__ void __launch_bounds__(FTHREADS, 2) kF() {
    int bid = blockIdx.x;
    int chk = bid % NCH2;
    int hwt = (bid / NCH2) % (HW / TH);
    int b   = bid / (NCH2 * (HW / TH));

    int tid = threadIdx.x;
    int pp  = tid & (NPP - 1);        // p-pair lane 0..7
    int hwl = tid >> 3;               // 0..27
    int hw  = hwt * TH + hwl;

    __shared__ __half2 vsm[NC][TH][NPP];
    for (int i = tid; i < NC * TH * NPP; i += FTHREADS) {
        int c  = i / (TH * NPP);
        int r  = i % (TH * NPP);
        int hl = r / NPP;
        int p2 = r % NPP;
        vsm[c][hl][p2] = *reinterpret_cast<const __half2*>(
            g_vs + (((size_t)(b * NC + c) * HW + hwt * TH + hl)) * NP + 2 * p2);
    }
    __syncthreads();

    float2 S2[NC];
#pragma unroll
    for (int c = 0; c < NC; c++) S2[c] = make_float2(0.0f, 0.0f);

    int B0 = chk * BCH2;
    int Bend = min(B0 + BCH2, NB);

    for (int B = B0; B < Bend; B++) {
        const __half* ub = g_u16 + ((((size_t)(b * NB + B) * NC) * HW + hw)) * NP + 2 * pp;
        __half2 x2[NC];
        float r4[4];

#pragma unroll
        for (int c = 0; c < NC; c++) {
            x2[c] = __ldcs(reinterpret_cast<const __half2*>(ub + (size_t)c * (HW * NP)));
            float2 xf = __half22float2(x2[c]);
            float2 vf = __half22float2(vsm[c][hwl][pp]);
            float t = xf.x * vf.x + xf.y * vf.y;
            t += __shfl_xor_sync(0xffffffffu, t, 1, 8);
            t += __shfl_xor_sync(0xffffffffu, t, 2, 8);
            t += __shfl_xor_sync(0xffffffffu, t, 4, 8);
            if ((c >> 2) == pp) r4[c & 3] = t;
        }

        // softmax over 32 c (4 per lane x 8 lanes)
        float m = fmaxf(fmaxf(r4[0], r4[1]), fmaxf(r4[2], r4[3]));
        m = fmaxf(m, __shfl_xor_sync(0xffffffffu, m, 1, 8));
        m = fmaxf(m, __shfl_xor_sync(0xffffffffu, m, 2, 8));
        m = fmaxf(m, __shfl_xor_sync(0xffffffffu, m, 4, 8));
        float w4[4];
        float ssum = 0.0f;
#pragma unroll
        for (int k = 0; k < 4; k++) { w4[k] = __expf(r4[k] - m); ssum += w4[k]; }
        ssum += __shfl_xor_sync(0xffffffffu, ssum, 1, 8);
        ssum += __shfl_xor_sync(0xffffffffu, ssum, 2, 8);
        ssum += __shfl_xor_sync(0xffffffffu, ssum, 4, 8);
        float inv = 1.0f / ssum;
#pragma unroll
        for (int k = 0; k < 4; k++) w4[k] *= inv;

        // accumulate S += w*u
#pragma unroll
        for (int c = 0; c < NC; c++) {
            float wc = __shfl_sync(0xffffffffu, w4[c & 3], c >> 2, 8);
            float2 xf = __half22float2(x2[c]);
            S2[c].x += wc * xf.x;
            S2[c].y += wc * xf.y;
        }
    }

    // write partial S
#pragma unroll
    for (int c = 0; c < NC; c++) {
        float2* dst = reinterpret_cast<float2*>(
            g_Sp + ((((size_t)(chk * BD + b) * NC + c) * HW + hw)) * NP + 2 * pp);
        __stcs(dst, S2[c]);
    }
}

// ---------------- Combine partials: squash; accumulate v_s or final output ----
template <int LAST>
__global__ void kC(float* __restrict__ vout, float* __restrict__ aout) {
    int t = blockIdx.x * blockDim.x + threadIdx.x;    // 25088
    int hw = t % HW;
    int rest = t / HW;
    int c = rest % NC;
    int b = rest / NC;

    float s[NP];
#pragma unroll
    for (int p = 0; p < NP; p++) s[p] = 0.0f;
#pragma unroll
    for (int chk = 0; chk < NCH2; chk++) {
        const float* sp = g_Sp + ((((size_t)(chk * BD + b) * NC + c) * HW + hw)) * NP;
#pragma unroll
        for (int p = 0; p < NP; p++) s[p] += sp[p];
    }
    float invd = g_invd[(b * NC + c) * HW + hw];
    float nv = EPSF;
#pragma unroll
    for (int p = 0; p < NP; p++) { s[p] *= invd; nv += s[p] * s[p]; }
    nv = sqrtf(nv);
    float f = 1.0f / (1.0f + nv);

    if (!LAST) {
        // g_vs <- invd*v0 + invd*v1  (r2 = <u_s, v0+v1>, so no r tensor needed)
        float fs = f * invd;
        uint4* dst = reinterpret_cast<uint4*>(g_vs + ((size_t)((b * NC + c) * HW + hw)) * NP);
        HPack old;
        old.u4[0] = dst[0];
        old.u4[1] = dst[1];
        HPack pk;
#pragma unroll
        for (int j = 0; j < 8; j++) {
            float2 o2 = __half22float2(old.h2[j]);
            pk.h2[j] = __floats2half2_rn(s[2 * j] * fs + o2.x, s[2 * j + 1] * fs + o2.y);
        }
        dst[0] = pk.u4[0];
        dst[1] = pk.u4[1];
    } else {
        float an = EPSF;
#pragma unroll
        for (int p = 0; p < NP; p++) {
            float v = s[p] * f;
            vout[((b * NC + c) * NP + p) * HW + hw] = v;
            an += v * v;
        }
        aout[(b * NC + c) * HW + hw] = sqrtf(an);
    }
}

// ---------------- launch ------------------------------------------------------
extern "C" void kernel_launch(void* const* d_in, const int* in_sizes, int n_in,
                              void* d_out, int out_size) {
    const float* u = (const float*)d_in[0];
    float* out = (float*)d_out;
    float* out_v = out;                       // 4*32*16*196 = 401408
    float* out_a = out + BD * NC * NP * HW;   // 4*32*196    = 25088

    const int FGRID = BD * (HW / TH) * NCH2;  // 280

    kA1<<<392, 256>>>(u);                     // norms + Sum_B u + u16 transpose
    kA2<<<98, 256>>>();                       // inv_d, v0s
    kF<<<FGRID, FTHREADS>>>();                // w1 = softmax(<u,v0s>); S1 partials
    kC<0><<<98, 256>>>(nullptr, nullptr);     // v1; g_vs = invd*(v0+v1)
    kF<<<FGRID, FTHREADS>>>();                // w2 = softmax(<u,v0s+v1s>); S2 partials
    kC<1><<<98, 256>>>(out_v, out_a);         // v2, a_out
}

// round 10
// speedup vs baseline: 1.0876x; 1.0692x over previous
#include <cuda_runtime.h>
#include <cuda_fp16.h>
#include <math.h>

// CapsuleRouting: u (4,288,32,16,14,14) f32, a unused.
// out = concat(v (4,32,16,14,14), a_out (4,32,14,14))
//
// r logits are linear in v => r2 = <u_s, v0+v1>; no r tensor.
// u transposed once to fp16 (b,B,c,hw,p); each routing iter streams it once.
// All small kernels are 8-lane p-pair parallel (shuffle norm reductions).

#define BD 4
#define NB 288
#define NC 32
#define NP 16
#define HW 196
#define NCHUNK 4
#define BCH (NB / NCHUNK)   // 72
#define EPSF 1e-5f

#define TH 28
#define NPP 8
#define FTHREADS (TH * NPP) // 224
#define NCH2 10
#define BCH2 29             // ceil(288/10)

// ---------------- scratch ------------------------------------------------------
__device__ __half g_u16[(size_t)BD * NB * NC * HW * NP];   // 231MB (b,B,c,hw,p)
__device__ float  g_S0p[NCHUNK * BD * NC * HW * NP];       // p-innermost
__device__ float  g_mxp[NCHUNK * BD * NC * HW];
__device__ float  g_mnp[NCHUNK * BD * NC * HW];
__device__ float  g_invd[BD * NC * HW];
__device__ __half g_vs[BD * NC * HW * NP];                 // invd*v0, then invd*(v0+v1)
__device__ float  g_Sp[NCH2 * BD * NC * HW * NP];          // (chk,b,c,hw,p)

union HPack { __half2 h2[8]; uint4 u4[2]; };

__device__ __forceinline__ float red8(float v) {
    v += __shfl_xor_sync(0xffffffffu, v, 1, 8);
    v += __shfl_xor_sync(0xffffffffu, v, 2, 8);
    v += __shfl_xor_sync(0xffffffffu, v, 4, 8);
    return v;
}

// ---------------- Pass A1: norms -> chunked max/min; Sum_B u; emit u16 --------
__global__ void kA1(const float* __restrict__ u) {
    int t = blockIdx.x * blockDim.x + threadIdx.x;    // 100352
    int hw = t % HW;
    int rest = t / HW;
    int c = rest % NC; rest /= NC;
    int b = rest % BD;
    int ch = rest / BD;

    float s[NP];
#pragma unroll
    for (int p = 0; p < NP; p++) s[p] = 0.0f;
    float mx = -1e30f, mn = 1e30f;

    const float* up = u + ((size_t)((b * NB + ch * BCH) * NC + c)) * (NP * HW) + hw;
    size_t u16base = (((size_t)(b * NB + ch * BCH) * NC + c) * HW + hw) * NP;

    for (int i = 0; i < BCH; i++) {
        float x[NP];
        float nrm = EPSF;
#pragma unroll
        for (int p = 0; p < NP; p++) {
            x[p] = __ldcs(up + p * HW);
            s[p] += x[p];
            nrm += x[p] * x[p];
        }
        nrm = sqrtf(nrm);
        mx = fmaxf(mx, nrm);
        mn = fminf(mn, nrm);

        HPack pk;
#pragma unroll
        for (int j = 0; j < 8; j++) pk.h2[j] = __floats2half2_rn(x[2 * j], x[2 * j + 1]);
        uint4* dst = reinterpret_cast<uint4*>(g_u16 + u16base);
        __stcs(dst + 0, pk.u4[0]);
        __stcs(dst + 1, pk.u4[1]);

        up += (size_t)NC * NP * HW;
        u16base += (size_t)NC * HW * NP;
    }
    int o = (ch * BD + b) * NC + c;
    float4* sp = reinterpret_cast<float4*>(g_S0p + ((size_t)o * HW + hw) * NP);
#pragma unroll
    for (int j = 0; j < 4; j++)
        sp[j] = make_float4(s[4 * j], s[4 * j + 1], s[4 * j + 2], s[4 * j + 3]);
    g_mxp[o * HW + hw] = mx;
    g_mnp[o * HW + hw] = mn;
}

// ---------------- Pass A2 (lane-parallel): inv_d, v0s = invd*squash(S0/32*invd)
__global__ void kA2() {
    int t = blockIdx.x * blockDim.x + threadIdx.x;    // 25088*8
    int pp = t & (NPP - 1);
    int idx = t >> 3;
    int hw = idx % HW;
    int rest = idx / HW;
    int c = rest % NC;
    int b = rest / NC;

    float2 s2 = make_float2(0.0f, 0.0f);
    float mx = -1e30f, mn = 1e30f;
#pragma unroll
    for (int ch = 0; ch < NCHUNK; ch++) {
        int o = (ch * BD + b) * NC + c;
        mx = fmaxf(mx, g_mxp[o * HW + hw]);
        mn = fminf(mn, g_mnp[o * HW + hw]);
        float2 v = *reinterpret_cast<const float2*>(
            g_S0p + ((size_t)o * HW + hw) * NP + 2 * pp);
        s2.x += v.x; s2.y += v.y;
    }
    float invd = 1.0f / (mx - mn);
    if (pp == 0) g_invd[(b * NC + c) * HW + hw] = invd;

    float scl = invd * (1.0f / (float)NC);
    s2.x *= scl; s2.y *= scl;
    float nv = sqrtf(red8(s2.x * s2.x + s2.y * s2.y) + EPSF);
    float f = invd / (1.0f + nv);
    *reinterpret_cast<__half2*>(g_vs + ((size_t)((b * NC + c) * HW + hw)) * NP + 2 * pp) =
        __floats2half2_rn(s2.x * f, s2.y * f);
}

// ---------------- Fused routing iteration: read u16 once ----------------------
__global__ void __launch_bounds__(FTHREADS, 2) kF() {
    int bid = blockIdx.x;
    int chk = bid % NCH2;
    int hwt = (bid / NCH2) % (HW / TH);
    int b   = bid / (NCH2 * (HW / TH));

    int tid = threadIdx.x;
    int pp  = tid & (NPP - 1);
    int hwl = tid >> 3;
    int hw  = hwt * TH + hwl;

    __shared__ __half2 vsm[NC][TH][NPP];
    for (int i = tid; i < NC * TH * NPP; i += FTHREADS) {
        int c  = i / (TH * NPP);
        int r  = i % (TH * NPP);
        int hl = r / NPP;
        int p2 = r % NPP;
        vsm[c][hl][p2] = *reinterpret_cast<const __half2*>(
            g_vs + (((size_t)(b * NC + c) * HW + hwt * TH + hl)) * NP + 2 * p2);
    }
    __syncthreads();

    float2 S2[NC];
#pragma unroll
    for (int c = 0; c < NC; c++) S2[c] = make_float2(0.0f, 0.0f);

    int B0 = chk * BCH2;
    int Bend = min(B0 + BCH2, NB);

    for (int B = B0; B < Bend; B++) {
        const __half* ub = g_u16 + ((((size_t)(b * NB + B) * NC) * HW + hw)) * NP + 2 * pp;
        __half2 x2[NC];
        float r4[4];

#pragma unroll
        for (int c = 0; c < NC; c++) {
            x2[c] = __ldcs(reinterpret_cast<const __half2*>(ub + (size_t)c * (HW * NP)));
            float2 xf = __half22float2(x2[c]);
            float2 vf = __half22float2(vsm[c][hwl][pp]);
            float t = red8(xf.x * vf.x + xf.y * vf.y);
            if ((c >> 2) == pp) r4[c & 3] = t;
        }

        float m = fmaxf(fmaxf(r4[0], r4[1]), fmaxf(r4[2], r4[3]));
        m = fmaxf(m, __shfl_xor_sync(0xffffffffu, m, 1, 8));
        m = fmaxf(m, __shfl_xor_sync(0xffffffffu, m, 2, 8));
        m = fmaxf(m, __shfl_xor_sync(0xffffffffu, m, 4, 8));
        float w4[4];
        float ssum = 0.0f;
#pragma unroll
        for (int k = 0; k < 4; k++) { w4[k] = __expf(r4[k] - m); ssum += w4[k]; }
        ssum = red8(ssum);
        float inv = 1.0f / ssum;
#pragma unroll
        for (int k = 0; k < 4; k++) w4[k] *= inv;

#pragma unroll
        for (int c = 0; c < NC; c++) {
            float wc = __shfl_sync(0xffffffffu, w4[c & 3], c >> 2, 8);
            float2 xf = __half22float2(x2[c]);
            S2[c].x += wc * xf.x;
            S2[c].y += wc * xf.y;
        }
    }

#pragma unroll
    for (int c = 0; c < NC; c++) {
        float2* dst = reinterpret_cast<float2*>(
            g_Sp + ((((size_t)(chk * BD + b) * NC + c) * HW + hw)) * NP + 2 * pp);
        __stcs(dst, S2[c]);
    }
}

// ---------------- Combine partials (lane-parallel): squash; vs-accum / output -
template <int LAST>
__global__ void kC(float* __restrict__ vout, float* __restrict__ aout) {
    int t = blockIdx.x * blockDim.x + threadIdx.x;    // 25088*8
    int pp = t & (NPP - 1);
    int idx = t >> 3;
    int hw = idx % HW;
    int rest = idx / HW;
    int c = rest % NC;
    int b = rest / NC;

    float2 s2 = make_float2(0.0f, 0.0f);
#pragma unroll
    for (int chk = 0; chk < NCH2; chk++) {
        float2 v = *reinterpret_cast<const float2*>(
            g_Sp + ((((size_t)(chk * BD + b) * NC + c) * HW + hw)) * NP + 2 * pp);
        s2.x += v.x; s2.y += v.y;
    }
    float invd = g_invd[(b * NC + c) * HW + hw];
    s2.x *= invd; s2.y *= invd;
    float nsq = red8(s2.x * s2.x + s2.y * s2.y);
    float nv = sqrtf(nsq + EPSF);
    float f = 1.0f / (1.0f + nv);

    if (!LAST) {
        float fs = f * invd;
        __half2* dst = reinterpret_cast<__half2*>(
            g_vs + ((size_t)((b * NC + c) * HW + hw)) * NP + 2 * pp);
        float2 o2 = __half22float2(*dst);
        *dst = __floats2half2_rn(s2.x * fs + o2.x, s2.y * fs + o2.y);
    } else {
        float vx = s2.x * f, vy = s2.y * f;
        vout[((b * NC + c) * NP + 2 * pp) * HW + hw] = vx;
        vout[((b * NC + c) * NP + 2 * pp + 1) * HW + hw] = vy;
        if (pp == 0) {
            float an = sqrtf(f * f * nsq + EPSF);
            aout[(b * NC + c) * HW + hw] = an;
        }
    }
}

// ---------------- launch ------------------------------------------------------
extern "C" void kernel_launch(void* const* d_in, const int* in_sizes, int n_in,
                              void* d_out, int out_size) {
    const float* u = (const float*)d_in[0];
    float* out = (float*)d_out;
    float* out_v = out;                       // 4*32*16*196 = 401408
    float* out_a = out + BD * NC * NP * HW;   // 4*32*196    = 25088

    const int FGRID = BD * (HW / TH) * NCH2;  // 280
    const int SGRID = (BD * NC * HW * NPP) / 256;  // 784

    kA1<<<392, 256>>>(u);                     // norms + Sum_B u + u16 transpose
    kA2<<<SGRID, 256>>>();                    // inv_d, v0s
    kF<<<FGRID, FTHREADS>>>();                // w1 = softmax(<u,v0s>); S1 partials
    kC<0><<<SGRID, 256>>>(nullptr, nullptr);  // g_vs = invd*(v0+v1)
    kF<<<FGRID, FTHREADS>>>();                // w2; S2 partials
    kC<1><<<SGRID, 256>>>(out_v, out_a);      // v2, a_out
}